// round 10
// baseline (speedup 1.0000x reference)
#include <cuda_runtime.h>
#include <cstddef>

// Problem constants (fixed shapes from reference setup_inputs)
#define DIM   576
#define NQ    2048
#define NS    64
#define LFR   8
#define MROWS (NQ * LFR)   // 16384 query frames
#define NCOLS (NS * LFR)   // 512 support frames
#define EPSF  0.01f

// Scratch: per-frame L2 norms (query frames first, then support frames)
__device__ float g_norms[MROWS + NCOLS];

// ---------------------------------------------------------------------------
// Kernel 1: frame norms. One warp per 576-dim vector.
// ---------------------------------------------------------------------------
__global__ void norms_kernel(const float* __restrict__ q,
                             const float* __restrict__ s) {
    int warp = (blockIdx.x * blockDim.x + threadIdx.x) >> 5;
    int lane = threadIdx.x & 31;
    if (warp >= MROWS + NCOLS) return;
    const float* base = (warp < MROWS)
        ? (q + (size_t)warp * DIM)
        : (s + (size_t)(warp - MROWS) * DIM);
    float acc = 0.f;
#pragma unroll
    for (int i = 0; i < DIM / 32; i++) {          // 18 iterations, coalesced
        float v = base[lane + i * 32];
        acc = fmaf(v, v, acc);
    }
#pragma unroll
    for (int o = 16; o; o >>= 1) acc += __shfl_xor_sync(0xffffffffu, acc, o);
    if (lane == 0) g_norms[warp] = sqrtf(acc);
}

// ---------------------------------------------------------------------------
// Soft-min helpers, lambda = 0.5  ->  softmin(t) = min - 0.5*log(sum exp(-2(t-min)))
// Stable form identical to jax.nn.logsumexp on -t/lambda.
// ---------------------------------------------------------------------------
__device__ __forceinline__ float softmin2(float a, float b) {
    float mn = fminf(a, b), mx = fmaxf(a, b);
    return mn - 0.5f * __logf(1.f + __expf(-2.f * (mx - mn)));
}
__device__ __forceinline__ float softmin3(float a, float b, float c) {
    float mn = fminf(fminf(a, b), c);
    float ssum = __expf(-2.f * (a - mn)) + __expf(-2.f * (b - mn))
               + __expf(-2.f * (c - mn));
    return mn - 0.5f * __logf(ssum);
}

// ---------------------------------------------------------------------------
// OTAM DP over an 8x8 tile held in registers. Faithful to OTAM_cum_dist_v2:
// pad last dim (1,1) with zeros -> W = 10 columns; row 0 is a plain cumsum;
// rows 1..7: cum[l,m] = d[l,m] + softmin(diag, left, up) where the 'up' term
// is only included for m == 1 and m == W-1 (the pad column, d = 0).
// TR=true runs the DP on the transposed tile.
// ---------------------------------------------------------------------------
template <bool TR>
__device__ __forceinline__ float otam_dp(const float (&t)[8][8]) {
    float prev[10], cur[10];
    prev[0] = 0.f;
#pragma unroll
    for (int m = 1; m <= 8; m++)
        prev[m] = prev[m - 1] + (TR ? t[m - 1][0] : t[0][m - 1]);
    prev[9] = prev[8];                       // pad column: d = 0

#pragma unroll
    for (int l = 1; l < 8; l++) {
        float left = 0.f;                    // cum[l, 0] = 0
        cur[0] = 0.f;
#pragma unroll
        for (int m = 1; m <= 9; m++) {
            float dm = (m <= 8) ? (TR ? t[m - 1][l] : t[l][m - 1]) : 0.f;
            float v;
            if (m == 1 || m == 9)
                v = softmin3(prev[m - 1], left, prev[m]);
            else
                v = softmin2(prev[m - 1], left);
            left = dm + v;
            cur[m] = left;
        }
#pragma unroll
        for (int m = 0; m < 10; m++) prev[m] = cur[m];
    }
    return prev[9];
}

// ---------------------------------------------------------------------------
// Kernel 2: fused cosine-distance GEMM + OTAM DP.
// BM=BN=128, BK=16, 256 threads, contiguous 8x8 micro-tile per thread so each
// thread's accumulator IS one (q,s) 8x8 frame-distance tile.
// ---------------------------------------------------------------------------
#define BK  16
#define BM  128
#define BN  128
#define LDA (BM + 4)   // smem pad; row stride 132 floats = 528B (16B aligned)

__global__ __launch_bounds__(256, 2)
void fused_otam_kernel(const float* __restrict__ A,   // query  [MROWS, DIM]
                       const float* __restrict__ B,   // support[NCOLS, DIM]
                       float* __restrict__ out) {     // [NQ, NS]
    __shared__ float As[BK][LDA];
    __shared__ float Bs[BK][LDA];
    __shared__ float qn[BM];
    __shared__ float sn[BN];

    const int tid = threadIdx.x;
    const int tx  = tid & 15;     // 0..15  -> support group
    const int ty  = tid >> 4;     // 0..15  -> query group
    const int r0  = blockIdx.y * BM;
    const int c0  = blockIdx.x * BN;

    if (tid < BM) qn[tid] = g_norms[r0 + tid];
    else          sn[tid - BM] = g_norms[MROWS + c0 + (tid - BM)];

    float acc[8][8];
#pragma unroll
    for (int i = 0; i < 8; i++)
#pragma unroll
        for (int j = 0; j < 8; j++) acc[i][j] = 0.f;

    for (int k0 = 0; k0 < DIM; k0 += BK) {
        // stage A/B tiles (transposed) into smem; 2 float4 per thread per tile
#pragma unroll
        for (int it = 0; it < 2; it++) {
            int f   = it * 256 + tid;        // 0..511
            int row = f >> 2;                // 0..127
            int c4  = (f & 3) << 2;          // 0,4,8,12
            float4 va = *(const float4*)(A + (size_t)(r0 + row) * DIM + k0 + c4);
            As[c4 + 0][row] = va.x; As[c4 + 1][row] = va.y;
            As[c4 + 2][row] = va.z; As[c4 + 3][row] = va.w;
            float4 vb = *(const float4*)(B + (size_t)(c0 + row) * DIM + k0 + c4);
            Bs[c4 + 0][row] = vb.x; Bs[c4 + 1][row] = vb.y;
            Bs[c4 + 2][row] = vb.z; Bs[c4 + 3][row] = vb.w;
        }
        __syncthreads();

#pragma unroll
        for (int kk = 0; kk < BK; kk++) {
            float4 a0 = *(const float4*)&As[kk][ty * 8];
            float4 a1 = *(const float4*)&As[kk][ty * 8 + 4];
            float4 b0 = *(const float4*)&Bs[kk][tx * 8];
            float4 b1 = *(const float4*)&Bs[kk][tx * 8 + 4];
            float a[8] = {a0.x, a0.y, a0.z, a0.w, a1.x, a1.y, a1.z, a1.w};
            float b[8] = {b0.x, b0.y, b0.z, b0.w, b1.x, b1.y, b1.z, b1.w};
#pragma unroll
            for (int i = 0; i < 8; i++)
#pragma unroll
                for (int j = 0; j < 8; j++)
                    acc[i][j] = fmaf(a[i], b[j], acc[i][j]);
        }
        __syncthreads();
    }

    // Normalize in place: dist = 1 - num / (|q||s| + eps)
    float qnl[8], snl[8];
#pragma unroll
    for (int i = 0; i < 8; i++) { qnl[i] = qn[ty * 8 + i]; snl[i] = sn[tx * 8 + i]; }
#pragma unroll
    for (int i = 0; i < 8; i++)
#pragma unroll
        for (int j = 0; j < 8; j++)
            acc[i][j] = 1.f - __fdividef(acc[i][j], fmaf(qnl[i], snl[j], EPSF));

    // OTAM DP on the tile and its transpose; meta_logit = -(c1 + c2)
    float r = otam_dp<false>(acc) + otam_dp<true>(acc);

    int qidx = (r0 >> 3) + ty;    // blockIdx.y*16 + ty
    int sidx = (c0 >> 3) + tx;    // blockIdx.x*16 + tx
    out[qidx * NS + sidx] = -r;
}

// ---------------------------------------------------------------------------
// Launch
// ---------------------------------------------------------------------------
extern "C" void kernel_launch(void* const* d_in, const int* in_sizes, int n_in,
                              void* d_out, int out_size) {
    const float* support;
    const float* query;
    // metadata order: support_features first, but disambiguate by size anyway
    if (in_sizes[0] == NCOLS * DIM) {
        support = (const float*)d_in[0];
        query   = (const float*)d_in[1];
    } else {
        support = (const float*)d_in[1];
        query   = (const float*)d_in[0];
    }
    float* out = (float*)d_out;

    // norms: one warp per vector, 8 warps/block
    int nvec   = MROWS + NCOLS;                 // 16896
    int nblk   = (nvec + 7) / 8;                // 2112
    norms_kernel<<<nblk, 256>>>(query, support);

    dim3 grid(NCOLS / BN, MROWS / BM);          // (4, 128)
    fused_otam_kernel<<<grid, 256>>>(query, support, out);
}

// round 15
// speedup vs baseline: 1.0001x; 1.0001x over previous
#include <cuda_runtime.h>
#include <cstddef>

// Problem constants (fixed shapes from reference setup_inputs)
#define DIM   576
#define NQ    2048
#define NS    64
#define LFR   8
#define MROWS (NQ * LFR)   // 16384 query frames
#define NCOLS (NS * LFR)   // 512 support frames
#define EPSF  0.01f

// Scratch: per-frame L2 norms (query frames first, then support frames)
__device__ float g_norms[MROWS + NCOLS];

// ---------------------------------------------------------------------------
// Kernel 1: frame norms. One warp per 576-dim vector.
// ---------------------------------------------------------------------------
__global__ void norms_kernel(const float* __restrict__ q,
                             const float* __restrict__ s) {
    int warp = (blockIdx.x * blockDim.x + threadIdx.x) >> 5;
    int lane = threadIdx.x & 31;
    if (warp >= MROWS + NCOLS) return;
    const float* base = (warp < MROWS)
        ? (q + (size_t)warp * DIM)
        : (s + (size_t)(warp - MROWS) * DIM);
    float acc = 0.f;
#pragma unroll
    for (int i = 0; i < DIM / 32; i++) {          // 18 iterations, coalesced
        float v = base[lane + i * 32];
        acc = fmaf(v, v, acc);
    }
#pragma unroll
    for (int o = 16; o; o >>= 1) acc += __shfl_xor_sync(0xffffffffu, acc, o);
    if (lane == 0) g_norms[warp] = sqrtf(acc);
}

// ---------------------------------------------------------------------------
// Soft-min helpers, lambda = 0.5  ->  softmin(t) = min - 0.5*log(sum exp(-2(t-min)))
// Stable form identical to jax.nn.logsumexp on -t/lambda.
// ---------------------------------------------------------------------------
__device__ __forceinline__ float softmin2(float a, float b) {
    float mn = fminf(a, b), mx = fmaxf(a, b);
    return mn - 0.5f * __logf(1.f + __expf(-2.f * (mx - mn)));
}
__device__ __forceinline__ float softmin3(float a, float b, float c) {
    float mn = fminf(fminf(a, b), c);
    float ssum = __expf(-2.f * (a - mn)) + __expf(-2.f * (b - mn))
               + __expf(-2.f * (c - mn));
    return mn - 0.5f * __logf(ssum);
}

// ---------------------------------------------------------------------------
// OTAM DP over an 8x8 tile held in registers. Faithful to OTAM_cum_dist_v2:
// pad last dim (1,1) with zeros -> W = 10 columns; row 0 is a plain cumsum;
// rows 1..7: cum[l,m] = d[l,m] + softmin(diag, left, up) where the 'up' term
// is only included for m == 1 and m == W-1 (the pad column, d = 0).
// TR=true runs the DP on the transposed tile.
// ---------------------------------------------------------------------------
template <bool TR>
__device__ __forceinline__ float otam_dp(const float (&t)[8][8]) {
    float prev[10], cur[10];
    prev[0] = 0.f;
#pragma unroll
    for (int m = 1; m <= 8; m++)
        prev[m] = prev[m - 1] + (TR ? t[m - 1][0] : t[0][m - 1]);
    prev[9] = prev[8];                       // pad column: d = 0

#pragma unroll
    for (int l = 1; l < 8; l++) {
        float left = 0.f;                    // cum[l, 0] = 0
        cur[0] = 0.f;
#pragma unroll
        for (int m = 1; m <= 9; m++) {
            float dm = (m <= 8) ? (TR ? t[m - 1][l] : t[l][m - 1]) : 0.f;
            float v;
            if (m == 1 || m == 9)
                v = softmin3(prev[m - 1], left, prev[m]);
            else
                v = softmin2(prev[m - 1], left);
            left = dm + v;
            cur[m] = left;
        }
#pragma unroll
        for (int m = 0; m < 10; m++) prev[m] = cur[m];
    }
    return prev[9];
}

// ---------------------------------------------------------------------------
// Kernel 2: fused cosine-distance GEMM + OTAM DP.
// BM=BN=128, BK=16, 256 threads, contiguous 8x8 micro-tile per thread so each
// thread's accumulator IS one (q,s) 8x8 frame-distance tile.
// ---------------------------------------------------------------------------
#define BK  16
#define BM  128
#define BN  128
#define LDA (BM + 4)   // smem pad; row stride 132 floats = 528B (16B aligned)

__global__ __launch_bounds__(256, 2)
void fused_otam_kernel(const float* __restrict__ A,   // query  [MROWS, DIM]
                       const float* __restrict__ B,   // support[NCOLS, DIM]
                       float* __restrict__ out) {     // [NQ, NS]
    __shared__ float As[BK][LDA];
    __shared__ float Bs[BK][LDA];
    __shared__ float qn[BM];
    __shared__ float sn[BN];

    const int tid = threadIdx.x;
    const int tx  = tid & 15;     // 0..15  -> support group
    const int ty  = tid >> 4;     // 0..15  -> query group
    const int r0  = blockIdx.y * BM;
    const int c0  = blockIdx.x * BN;

    if (tid < BM) qn[tid] = g_norms[r0 + tid];
    else          sn[tid - BM] = g_norms[MROWS + c0 + (tid - BM)];

    float acc[8][8];
#pragma unroll
    for (int i = 0; i < 8; i++)
#pragma unroll
        for (int j = 0; j < 8; j++) acc[i][j] = 0.f;

    for (int k0 = 0; k0 < DIM; k0 += BK) {
        // stage A/B tiles (transposed) into smem; 2 float4 per thread per tile
#pragma unroll
        for (int it = 0; it < 2; it++) {
            int f   = it * 256 + tid;        // 0..511
            int row = f >> 2;                // 0..127
            int c4  = (f & 3) << 2;          // 0,4,8,12
            float4 va = *(const float4*)(A + (size_t)(r0 + row) * DIM + k0 + c4);
            As[c4 + 0][row] = va.x; As[c4 + 1][row] = va.y;
            As[c4 + 2][row] = va.z; As[c4 + 3][row] = va.w;
            float4 vb = *(const float4*)(B + (size_t)(c0 + row) * DIM + k0 + c4);
            Bs[c4 + 0][row] = vb.x; Bs[c4 + 1][row] = vb.y;
            Bs[c4 + 2][row] = vb.z; Bs[c4 + 3][row] = vb.w;
        }
        __syncthreads();

#pragma unroll
        for (int kk = 0; kk < BK; kk++) {
            float4 a0 = *(const float4*)&As[kk][ty * 8];
            float4 a1 = *(const float4*)&As[kk][ty * 8 + 4];
            float4 b0 = *(const float4*)&Bs[kk][tx * 8];
            float4 b1 = *(const float4*)&Bs[kk][tx * 8 + 4];
            float a[8] = {a0.x, a0.y, a0.z, a0.w, a1.x, a1.y, a1.z, a1.w};
            float b[8] = {b0.x, b0.y, b0.z, b0.w, b1.x, b1.y, b1.z, b1.w};
#pragma unroll
            for (int i = 0; i < 8; i++)
#pragma unroll
                for (int j = 0; j < 8; j++)
                    acc[i][j] = fmaf(a[i], b[j], acc[i][j]);
        }
        __syncthreads();
    }

    // Normalize in place: dist = 1 - num / (|q||s| + eps)
    float qnl[8], snl[8];
#pragma unroll
    for (int i = 0; i < 8; i++) { qnl[i] = qn[ty * 8 + i]; snl[i] = sn[tx * 8 + i]; }
#pragma unroll
    for (int i = 0; i < 8; i++)
#pragma unroll
        for (int j = 0; j < 8; j++)
            acc[i][j] = 1.f - __fdividef(acc[i][j], fmaf(qnl[i], snl[j], EPSF));

    // OTAM DP on the tile and its transpose; meta_logit = -(c1 + c2)
    float r = otam_dp<false>(acc) + otam_dp<true>(acc);

    int qidx = (r0 >> 3) + ty;    // blockIdx.y*16 + ty
    int sidx = (c0 >> 3) + tx;    // blockIdx.x*16 + tx
    out[qidx * NS + sidx] = -r;
}

// ---------------------------------------------------------------------------
// Launch
// ---------------------------------------------------------------------------
extern "C" void kernel_launch(void* const* d_in, const int* in_sizes, int n_in,
                              void* d_out, int out_size) {
    const float* support;
    const float* query;
    // metadata order: support_features first, but disambiguate by size anyway
    if (in_sizes[0] == NCOLS * DIM) {
        support = (const float*)d_in[0];
        query   = (const float*)d_in[1];
    } else {
        support = (const float*)d_in[1];
        query   = (const float*)d_in[0];
    }
    float* out = (float*)d_out;

    // norms: one warp per vector, 8 warps/block
    int nvec   = MROWS + NCOLS;                 // 16896
    int nblk   = (nvec + 7) / 8;                // 2112
    norms_kernel<<<nblk, 256>>>(query, support);

    dim3 grid(NCOLS / BN, MROWS / BM);          // (4, 128)
    fused_otam_kernel<<<grid, 256>>>(query, support, out);
}